// round 6
// baseline (speedup 1.0000x reference)
#include <cuda_runtime.h>
#include <cuda_bf16.h>
#include <cstdint>
#include <cstddef>

#define Bb 512
#define Tt 512
#define Ff 128
#define Uu 256
#define G4 1024   // 4*U

// ---------------- device scratch ----------------
__device__ float g_xz[(size_t)Bb * Tt * G4];          // precomputed x@kernel+bias
__device__ __nv_bfloat16 g_hh[2][Bb][Uu];             // h hi (bf16), double buffered
__device__ __nv_bfloat16 g_hl[2][Bb][Uu];             // h lo (bf16)
__device__ unsigned g_barg[16][32];                   // per-batch-group barrier (padded)

__global__ void reset_kernel() {
    int i = blockIdx.x * blockDim.x + threadIdx.x;
    if (i < Bb * Uu) {
        (&g_hh[0][0][0])[i] = __float2bfloat16(0.f);
        (&g_hl[0][0][0])[i] = __float2bfloat16(0.f);
    }
    if (i < 16 * 32) (&g_barg[0][0])[i] = 0u;
}

// ---------------- helpers ----------------
__device__ __forceinline__ void mma_bf16(float& d0, float& d1, float& d2, float& d3,
                                         unsigned a0, unsigned a1, unsigned a2, unsigned a3,
                                         unsigned b0, unsigned b1) {
    asm volatile("mma.sync.aligned.m16n8k16.row.col.f32.bf16.bf16.f32 "
                 "{%0,%1,%2,%3}, {%4,%5,%6,%7}, {%8,%9}, {%0,%1,%2,%3};"
                 : "+f"(d0), "+f"(d1), "+f"(d2), "+f"(d3)
                 : "r"(a0), "r"(a1), "r"(a2), "r"(a3), "r"(b0), "r"(b1));
}
__device__ __forceinline__ unsigned pk2(__nv_bfloat16 x, __nv_bfloat16 y) {
    __nv_bfloat162 t; t.x = x; t.y = y;
    return *reinterpret_cast<unsigned*>(&t);
}
__device__ __forceinline__ void split1(float v, __nv_bfloat16& h, __nv_bfloat16& l) {
    h = __float2bfloat16_rn(v);
    l = __float2bfloat16_rn(v - __bfloat162float(h));
}
__device__ __forceinline__ void cp_async16(void* sdst, const void* gsrc) {
    unsigned sa = (unsigned)__cvta_generic_to_shared(sdst);
    asm volatile("cp.async.cg.shared.global [%0], [%1], 16;" :: "r"(sa), "l"(gsrc));
}
__device__ __forceinline__ void ldsm4(unsigned& r0, unsigned& r1, unsigned& r2, unsigned& r3,
                                      const void* p) {
    unsigned sa = (unsigned)__cvta_generic_to_shared(p);
    asm volatile("ldmatrix.sync.aligned.m8n8.x4.shared.b16 {%0,%1,%2,%3}, [%4];"
                 : "=r"(r0), "=r"(r1), "=r"(r2), "=r"(r3) : "r"(sa));
}

// ================= Phase 1: XZ = x @ kernel + bias (bf16x3 mma) =================
// CTA tile 128M x 64N, K=128 single shot. 512 threads = 16 warps (4x4),
// warp tile 32x16. SMEM 104448 B -> 2 CTAs/SM (fill overlaps compute).
#define P1_STR 136

__global__ __launch_bounds__(512, 2) void xz_gemm(const float* __restrict__ x,
                                                  const float* __restrict__ wk,
                                                  const float* __restrict__ bias) {
    extern __shared__ char smc[];
    __nv_bfloat16* Ahi = (__nv_bfloat16*)smc;                   // [128][136]
    __nv_bfloat16* Alo = (__nv_bfloat16*)(smc + 34816);
    __nv_bfloat16* Bhi = (__nv_bfloat16*)(smc + 69632);         // [64 n][136 k]
    __nv_bfloat16* Blo = (__nv_bfloat16*)(smc + 87040);

    int tid  = threadIdx.x;
    int nblk = blockIdx.x, mblk = blockIdx.y;
    const float* xblk = x + (size_t)mblk * 128 * Ff;
    const float* wcol = wk + (size_t)nblk * 64;

    // A fill: x tile [128][128] fp32 -> split
    {
        int r = tid >> 2, q = tid & 3;
        const float* xr = xblk + (size_t)r * Ff;
#pragma unroll
        for (int jj = 0; jj < 8; jj++) {
            int col = 4 * q + 16 * jj;
            float4 v = *(const float4*)(xr + col);
            __nv_bfloat16 h0, h1, h2, h3, l0, l1, l2, l3;
            split1(v.x, h0, l0); split1(v.y, h1, l1);
            split1(v.z, h2, l2); split1(v.w, h3, l3);
            *(unsigned*)(Ahi + r * P1_STR + col)     = pk2(h0, h1);
            *(unsigned*)(Ahi + r * P1_STR + col + 2) = pk2(h2, h3);
            *(unsigned*)(Alo + r * P1_STR + col)     = pk2(l0, l1);
            *(unsigned*)(Alo + r * P1_STR + col + 2) = pk2(l2, l3);
        }
    }
    // B fill: Bs[n][k] = wk[k][nblk*64+n] -> split (64x128 entries)
#pragma unroll
    for (int i = 0; i < 16; i++) {
        int flat = tid + 512 * i;
        int k = flat >> 6, n = flat & 63;
        float v = wcol[(size_t)k * G4 + n];
        __nv_bfloat16 h, l; split1(v, h, l);
        Bhi[n * P1_STR + k] = h;
        Blo[n * P1_STR + k] = l;
    }
    __syncthreads();

    int w = tid >> 5, lane = tid & 31;
    int wm = w >> 2, wn = w & 3;
    int g = lane >> 2, tq = lane & 3;
    int mb = 32 * wm, nb = 16 * wn;

    float acc[2][2][4];
#pragma unroll
    for (int ni = 0; ni < 2; ni++) {
        float2 bv = *(const float2*)(bias + nblk * 64 + nb + 8 * ni + 2 * tq);
#pragma unroll
        for (int mi = 0; mi < 2; mi++) {
            acc[mi][ni][0] = bv.x; acc[mi][ni][1] = bv.y;
            acc[mi][ni][2] = bv.x; acc[mi][ni][3] = bv.y;
        }
    }

#pragma unroll 2
    for (int kc = 0; kc < 128; kc += 16) {
        unsigned bh[2][2], bl[2][2];
#pragma unroll
        for (int ni = 0; ni < 2; ni++) {
            const __nv_bfloat16* bp = Bhi + (nb + 8 * ni + g) * P1_STR + kc + 2 * tq;
            bh[ni][0] = *(const unsigned*)bp;
            bh[ni][1] = *(const unsigned*)(bp + 8);
            const __nv_bfloat16* bq = Blo + (nb + 8 * ni + g) * P1_STR + kc + 2 * tq;
            bl[ni][0] = *(const unsigned*)bq;
            bl[ni][1] = *(const unsigned*)(bq + 8);
        }
#pragma unroll
        for (int mi = 0; mi < 2; mi++) {
            const __nv_bfloat16* ap = Ahi + (mb + 16 * mi + g) * P1_STR + kc + 2 * tq;
            unsigned a0 = *(const unsigned*)ap;
            unsigned a1 = *(const unsigned*)(ap + 8 * P1_STR);
            unsigned a2 = *(const unsigned*)(ap + 8);
            unsigned a3 = *(const unsigned*)(ap + 8 * P1_STR + 8);
            const __nv_bfloat16* aq = Alo + (mb + 16 * mi + g) * P1_STR + kc + 2 * tq;
            unsigned e0 = *(const unsigned*)aq;
            unsigned e1 = *(const unsigned*)(aq + 8 * P1_STR);
            unsigned e2 = *(const unsigned*)(aq + 8);
            unsigned e3 = *(const unsigned*)(aq + 8 * P1_STR + 8);
#pragma unroll
            for (int ni = 0; ni < 2; ni++) {
                mma_bf16(acc[mi][ni][0], acc[mi][ni][1], acc[mi][ni][2], acc[mi][ni][3],
                         a0, a1, a2, a3, bh[ni][0], bh[ni][1]);
                mma_bf16(acc[mi][ni][0], acc[mi][ni][1], acc[mi][ni][2], acc[mi][ni][3],
                         a0, a1, a2, a3, bl[ni][0], bl[ni][1]);
                mma_bf16(acc[mi][ni][0], acc[mi][ni][1], acc[mi][ni][2], acc[mi][ni][3],
                         e0, e1, e2, e3, bh[ni][0], bh[ni][1]);
            }
        }
    }

    float* od = g_xz + ((size_t)mblk * 128) * G4 + nblk * 64;
#pragma unroll
    for (int mi = 0; mi < 2; mi++) {
#pragma unroll
        for (int ni = 0; ni < 2; ni++) {
            int row = mb + 16 * mi + g, col = nb + 8 * ni + 2 * tq;
            *(float2*)(od + (size_t)row * G4 + col)       = make_float2(acc[mi][ni][0], acc[mi][ni][1]);
            *(float2*)(od + (size_t)(row + 8) * G4 + col) = make_float2(acc[mi][ni][2], acc[mi][ni][3]);
        }
    }
}

// ================= Phase 2: persistent recurrence (bf16x3 mma v2) =================
// 128 CTAs = 16 batch-groups x 8 col-groups; CTA = 32 batches x 128 gate-cols.
// h exchanged as PRE-SPLIT bf16 hi/lo via global (producer splits once; consumers
// cp.async). Fragments via ldmatrix. Barrier scoped to the 8 CTAs of a batch-group.
#define RC_CTAS 128
#define WS 264     // W smem stride (bf16)
#define AS 264     // A(h) smem stride (bf16)
#define XSS 132    // xz smem stride (floats)
#define XSBUF (32 * XSS)
#define ZSS 136    // z smem stride (floats)

__global__ __launch_bounds__(256, 1) void lstm_rec(const float* __restrict__ rk,
                                                   const float* __restrict__ dw,
                                                   const float* __restrict__ db,
                                                   float* __restrict__ out) {
    extern __shared__ char smc[];
    __nv_bfloat16* Wh = (__nv_bfloat16*)smc;                    // [128][264]
    __nv_bfloat16* Wl = (__nv_bfloat16*)(smc + 67584);
    __nv_bfloat16* Ah = (__nv_bfloat16*)(smc + 135168);         // [32][264]
    __nv_bfloat16* Al = (__nv_bfloat16*)(smc + 152064);
    float* xs = (float*)(smc + 168960);                         // [2][32][132]
    float* zs = (float*)(smc + 202752);                         // [32][136]

    int tid   = threadIdx.x;
    int bg    = blockIdx.x >> 3;
    int cg    = blockIdx.x & 7;
    int bbase = bg * 32;
    int ubase = cg * 32;

    // one-time: weight slice -> bf16 hi/lo, layout Wh[j][k], j = gate*32 + u
    for (int i = tid; i < 128 * 256; i += 256) {
        int j = i >> 8, k = i & 255;
        int gate = j >> 5, u = j & 31;
        float v = rk[(size_t)k * G4 + gate * Uu + ubase + u];
        __nv_bfloat16 h, l; split1(v, h, l);
        Wh[j * WS + k] = h;
        Wl[j * WS + k] = l;
    }

    int w = tid >> 5, lane = tid & 31;
    int g = lane >> 2, tq = lane & 3;
    int nb = 16 * w;                 // warp covers local cols [16w,16w+16)
    int gb = tid >> 3;               // gate-layer batch
    int gu = (tid & 7) * 4;          // gate-layer unit base
    float cst[4] = {0.f, 0.f, 0.f, 0.f};

    // t-invariant ldmatrix lane-address components
    int aRow = lane & 15;
    int aK   = (lane >> 4) * 8;
    int bRow = nb + 8 * (lane >> 4) + (lane & 7);
    int bK   = 8 * ((lane >> 3) & 1);

    // prefetch xz tile for t=0 into xs buf 0
#pragma unroll
    for (int i = 0; i < 4; i++) {
        int flat4 = tid + 256 * i;
        int bbq = flat4 >> 5, rest = flat4 & 31, gg = rest >> 3, u4 = rest & 7;
        const float* gsrc = g_xz + ((size_t)(bbase + bbq) * Tt + 0) * G4 + gg * Uu + ubase + 4 * u4;
        cp_async16(xs + bbq * XSS + gg * 32 + 4 * u4, gsrc);
    }
    asm volatile("cp.async.commit_group;" ::: "memory");

    unsigned target = 0;

    for (int t = 0; t < Tt; t++) {
        int cur = t & 1, nxt = cur ^ 1;

        // stage h hi/lo tiles via cp.async (pre-split by producers)
#pragma unroll
        for (int i = 0; i < 4; i++) {
            int c = tid + 256 * i;       // 0..1023
            int row = c >> 5, o = (c & 31) * 8;
            cp_async16(Ah + row * AS + o, &g_hh[cur][bbase + row][o]);
            cp_async16(Al + row * AS + o, &g_hl[cur][bbase + row][o]);
        }
        asm volatile("cp.async.commit_group;" ::: "memory");
        asm volatile("cp.async.wait_group 0;" ::: "memory");   // h + xz(t) done
        __syncthreads();

        // acc init from xz tile
        float acc[2][2][4];
#pragma unroll
        for (int mi = 0; mi < 2; mi++) {
#pragma unroll
            for (int ni = 0; ni < 2; ni++) {
                const float* zp = xs + cur * XSBUF + (16 * mi + g) * XSS + nb + 8 * ni + 2 * tq;
                float2 a = *(const float2*)zp;
                float2 b = *(const float2*)(zp + 8 * XSS);
                acc[mi][ni][0] = a.x; acc[mi][ni][1] = a.y;
                acc[mi][ni][2] = b.x; acc[mi][ni][3] = b.y;
            }
        }

        // K loop: z += h @ Wr (3-pass bf16 split, ldmatrix fragments)
#pragma unroll 4
        for (int kc = 0; kc < 256; kc += 16) {
            unsigned bh0, bh1, bh2, bh3, bl0, bl1, bl2, bl3;
            ldsm4(bh0, bh1, bh2, bh3, Wh + bRow * WS + kc + bK);
            ldsm4(bl0, bl1, bl2, bl3, Wl + bRow * WS + kc + bK);
#pragma unroll
            for (int mi = 0; mi < 2; mi++) {
                unsigned a0, a1, a2, a3, e0, e1, e2, e3;
                ldsm4(a0, a1, a2, a3, Ah + (16 * mi + aRow) * AS + kc + aK);
                ldsm4(e0, e1, e2, e3, Al + (16 * mi + aRow) * AS + kc + aK);
                mma_bf16(acc[mi][0][0], acc[mi][0][1], acc[mi][0][2], acc[mi][0][3],
                         a0, a1, a2, a3, bh0, bh1);
                mma_bf16(acc[mi][1][0], acc[mi][1][1], acc[mi][1][2], acc[mi][1][3],
                         a0, a1, a2, a3, bh2, bh3);
                mma_bf16(acc[mi][0][0], acc[mi][0][1], acc[mi][0][2], acc[mi][0][3],
                         a0, a1, a2, a3, bl0, bl1);
                mma_bf16(acc[mi][1][0], acc[mi][1][1], acc[mi][1][2], acc[mi][1][3],
                         a0, a1, a2, a3, bl2, bl3);
                mma_bf16(acc[mi][0][0], acc[mi][0][1], acc[mi][0][2], acc[mi][0][3],
                         e0, e1, e2, e3, bh0, bh1);
                mma_bf16(acc[mi][1][0], acc[mi][1][1], acc[mi][1][2], acc[mi][1][3],
                         e0, e1, e2, e3, bh2, bh3);
            }
        }

        // bounce z through SMEM (decouple gate layout from mma fragments)
#pragma unroll
        for (int mi = 0; mi < 2; mi++) {
#pragma unroll
            for (int ni = 0; ni < 2; ni++) {
                float* zp = zs + (16 * mi + g) * ZSS + nb + 8 * ni + 2 * tq;
                *(float2*)zp             = make_float2(acc[mi][ni][0], acc[mi][ni][1]);
                *(float2*)(zp + 8 * ZSS) = make_float2(acc[mi][ni][2], acc[mi][ni][3]);
            }
        }
        __syncthreads();

        // gate layer: thread -> (batch gb, units gu..gu+3); producer-side split
        {
            const float* zr = zs + gb * ZSS + gu;
            float4 zi = *(const float4*)(zr + 0);
            float4 zf = *(const float4*)(zr + 32);
            float4 zg = *(const float4*)(zr + 64);
            float4 zo = *(const float4*)(zr + 96);
            float zia[4] = {zi.x, zi.y, zi.z, zi.w};
            float zfa[4] = {zf.x, zf.y, zf.z, zf.w};
            float zga[4] = {zg.x, zg.y, zg.z, zg.w};
            float zoa[4] = {zo.x, zo.y, zo.z, zo.w};
            __nv_bfloat16 hh4[4], hl4[4];
#pragma unroll
            for (int e = 0; e < 4; e++) {
                float ig = 1.f / (1.f + __expf(-zia[e]));
                float fg = 1.f / (1.f + __expf(-zfa[e]));
                float gg = fmaxf(zga[e], 0.f);
                float og = 1.f / (1.f + __expf(-zoa[e]));
                float cn = fg * cst[e] + ig * gg;
                cst[e] = cn;
                float hn = og * fmaxf(cn, 0.f);
                split1(hn, hh4[e], hl4[e]);
            }
            *(uint2*)(&g_hh[nxt][bbase + gb][ubase + gu]) =
                make_uint2(pk2(hh4[0], hh4[1]), pk2(hh4[2], hh4[3]));
            *(uint2*)(&g_hl[nxt][bbase + gb][ubase + gu]) =
                make_uint2(pk2(hl4[0], hl4[1]), pk2(hl4[2], hl4[3]));
        }

        // prefetch xz tile for t+1
        if (t + 1 < Tt) {
#pragma unroll
            for (int i = 0; i < 4; i++) {
                int flat4 = tid + 256 * i;
                int bbq = flat4 >> 5, rest = flat4 & 31, gg = rest >> 3, u4 = rest & 7;
                const float* gsrc = g_xz + ((size_t)(bbase + bbq) * Tt + (t + 1)) * G4 + gg * Uu + ubase + 4 * u4;
                cp_async16(xs + nxt * XSBUF + bbq * XSS + gg * 32 + 4 * u4, gsrc);
            }
            asm volatile("cp.async.commit_group;" ::: "memory");
        }

        // per-batch-group barrier (8 CTAs share one counter)
        __syncthreads();
        if (tid == 0) {
            __threadfence();
            atomicAdd(&g_barg[bg][0], 1u);
            target += 8;
            while (*((volatile unsigned*)&g_barg[bg][0]) < target) { }
            __threadfence();
        }
        __syncthreads();
    }

    // final dense: out[b] = h_T[b,:] . dw + db  (T even -> final h in buffer 0)
    if (cg == 0) {
        int b = tid >> 3, r = tid & 7;
        const __nv_bfloat16* hh = &g_hh[0][bbase + b][0];
        const __nv_bfloat16* hl = &g_hl[0][bbase + b][0];
        float s = 0.f;
#pragma unroll
        for (int j = 0; j < 32; j++) {
            int u = r + 8 * j;
            s += (__bfloat162float(hh[u]) + __bfloat162float(hl[u])) * dw[u];
        }
        s += __shfl_down_sync(0xffffffffu, s, 4);
        s += __shfl_down_sync(0xffffffffu, s, 2);
        s += __shfl_down_sync(0xffffffffu, s, 1);
        if (r == 0) out[bbase + b] = s + db[0];
    }
}

// ---------------- launch ----------------
extern "C" void kernel_launch(void* const* d_in, const int* in_sizes, int n_in,
                              void* d_out, int out_size) {
    const float* x    = (const float*)d_in[0];
    const float* wk   = (const float*)d_in[1];
    const float* rk   = (const float*)d_in[2];
    const float* bias = (const float*)d_in[3];
    const float* dw   = (const float*)d_in[4];
    const float* db   = (const float*)d_in[5];
    float* out = (float*)d_out;

    const int smem1 = 104448;   // phase-1: A 2x[128][136] + B 2x[64][136] bf16
    const int smem2 = 220160;   // phase-2: W hi/lo + A hi/lo + xs + zs
    cudaFuncSetAttribute(xz_gemm,  cudaFuncAttributeMaxDynamicSharedMemorySize, smem1);
    cudaFuncSetAttribute(lstm_rec, cudaFuncAttributeMaxDynamicSharedMemorySize, smem2);

    reset_kernel<<<(Bb * Uu + 255) / 256, 256>>>();
    xz_gemm<<<dim3(G4 / 64, (Bb * Tt) / 128), 512, smem1>>>(x, wk, bias);
    lstm_rec<<<RC_CTAS, 256, smem2>>>(rk, dw, db, out);
}

// round 11
// speedup vs baseline: 1.1783x; 1.1783x over previous
#include <cuda_runtime.h>
#include <cuda_fp16.h>
#include <cstdint>
#include <cstddef>

#define Bb 512
#define Tt 512
#define Ff 128
#define Uu 256
#define G4 1024   // 4*U

// ---------------- device scratch ----------------
__device__ float g_xz[(size_t)Bb * Tt * G4];          // precomputed x@kernel+bias
__device__ __half g_hv[2][Bb][Uu];                    // h (fp16), double buffered
__device__ unsigned g_barg[16][32];                   // per-batch-group barrier

__global__ void reset_kernel() {
    int i = blockIdx.x * blockDim.x + threadIdx.x;
    if (i < Bb * Uu) (&g_hv[0][0][0])[i] = __ushort_as_half(0);
    if (i < 16 * 32) (&g_barg[0][0])[i] = 0u;
}

// ---------------- helpers ----------------
__device__ __forceinline__ void mma_f16(float& d0, float& d1, float& d2, float& d3,
                                        unsigned a0, unsigned a1, unsigned a2, unsigned a3,
                                        unsigned b0, unsigned b1) {
    asm volatile("mma.sync.aligned.m16n8k16.row.col.f32.f16.f16.f32 "
                 "{%0,%1,%2,%3}, {%4,%5,%6,%7}, {%8,%9}, {%0,%1,%2,%3};"
                 : "+f"(d0), "+f"(d1), "+f"(d2), "+f"(d3)
                 : "r"(a0), "r"(a1), "r"(a2), "r"(a3), "r"(b0), "r"(b1));
}
__device__ __forceinline__ unsigned pk2(__half x, __half y) {
    __half2 t; t.x = x; t.y = y;
    return *reinterpret_cast<unsigned*>(&t);
}
__device__ __forceinline__ void split1(float v, __half& h, __half& l) {
    h = __float2half_rn(v);
    l = __float2half_rn(v - __half2float(h));
}
__device__ __forceinline__ void cp_async16(void* sdst, const void* gsrc) {
    unsigned sa = (unsigned)__cvta_generic_to_shared(sdst);
    asm volatile("cp.async.cg.shared.global [%0], [%1], 16;" :: "r"(sa), "l"(gsrc));
}
__device__ __forceinline__ void ldsm4(unsigned& r0, unsigned& r1, unsigned& r2, unsigned& r3,
                                      const void* p) {
    unsigned sa = (unsigned)__cvta_generic_to_shared(p);
    asm volatile("ldmatrix.sync.aligned.m8n8.x4.shared.b16 {%0,%1,%2,%3}, [%4];"
                 : "=r"(r0), "=r"(r1), "=r"(r2), "=r"(r3) : "r"(sa));
}

// ================= Phase 1: XZ = x @ kernel + bias (fp16 2-pass mma) =================
// CTA tile 128M x 64N, K=128. 512 threads = 16 warps (4x4), warp tile 32x16.
// A = x rounded to fp16 (unsplit); B = kernel split hi/lo fp16.
#define P1_STR 136

__global__ __launch_bounds__(512, 2) void xz_gemm(const float* __restrict__ x,
                                                  const float* __restrict__ wk,
                                                  const float* __restrict__ bias) {
    extern __shared__ char smc[];
    __half* Ax  = (__half*)smc;                        // [128][136]
    __half* Bhi = (__half*)(smc + 34816);              // [64 n][136 k]
    __half* Blo = (__half*)(smc + 52224);

    int tid  = threadIdx.x;
    int nblk = blockIdx.x, mblk = blockIdx.y;
    const float* xblk = x + (size_t)mblk * 128 * Ff;
    const float* wcol = wk + (size_t)nblk * 64;

    // A fill: x tile [128][128] fp32 -> fp16
    {
        int r = tid >> 2, q = tid & 3;
        const float* xr = xblk + (size_t)r * Ff;
#pragma unroll
        for (int jj = 0; jj < 8; jj++) {
            int col = 4 * q + 16 * jj;
            float4 v = *(const float4*)(xr + col);
            *(unsigned*)(Ax + r * P1_STR + col)     = pk2(__float2half_rn(v.x), __float2half_rn(v.y));
            *(unsigned*)(Ax + r * P1_STR + col + 2) = pk2(__float2half_rn(v.z), __float2half_rn(v.w));
        }
    }
    // B fill: Bs[n][k] = wk[k][nblk*64+n] -> split hi/lo
#pragma unroll
    for (int i = 0; i < 16; i++) {
        int flat = tid + 512 * i;
        int k = flat >> 6, n = flat & 63;
        float v = wcol[(size_t)k * G4 + n];
        __half h, l; split1(v, h, l);
        Bhi[n * P1_STR + k] = h;
        Blo[n * P1_STR + k] = l;
    }
    __syncthreads();

    int w = tid >> 5, lane = tid & 31;
    int wm = w >> 2, wn = w & 3;
    int g = lane >> 2, tq = lane & 3;
    int mb = 32 * wm, nb = 16 * wn;

    float acc[2][2][4];
#pragma unroll
    for (int ni = 0; ni < 2; ni++) {
        float2 bv = *(const float2*)(bias + nblk * 64 + nb + 8 * ni + 2 * tq);
#pragma unroll
        for (int mi = 0; mi < 2; mi++) {
            acc[mi][ni][0] = bv.x; acc[mi][ni][1] = bv.y;
            acc[mi][ni][2] = bv.x; acc[mi][ni][3] = bv.y;
        }
    }

#pragma unroll 2
    for (int kc = 0; kc < 128; kc += 16) {
        unsigned bh[2][2], bl[2][2];
#pragma unroll
        for (int ni = 0; ni < 2; ni++) {
            const __half* bp = Bhi + (nb + 8 * ni + g) * P1_STR + kc + 2 * tq;
            bh[ni][0] = *(const unsigned*)bp;
            bh[ni][1] = *(const unsigned*)(bp + 8);
            const __half* bq = Blo + (nb + 8 * ni + g) * P1_STR + kc + 2 * tq;
            bl[ni][0] = *(const unsigned*)bq;
            bl[ni][1] = *(const unsigned*)(bq + 8);
        }
#pragma unroll
        for (int mi = 0; mi < 2; mi++) {
            const __half* ap = Ax + (mb + 16 * mi + g) * P1_STR + kc + 2 * tq;
            unsigned a0 = *(const unsigned*)ap;
            unsigned a1 = *(const unsigned*)(ap + 8 * P1_STR);
            unsigned a2 = *(const unsigned*)(ap + 8);
            unsigned a3 = *(const unsigned*)(ap + 8 * P1_STR + 8);
#pragma unroll
            for (int ni = 0; ni < 2; ni++) {
                mma_f16(acc[mi][ni][0], acc[mi][ni][1], acc[mi][ni][2], acc[mi][ni][3],
                        a0, a1, a2, a3, bh[ni][0], bh[ni][1]);
                mma_f16(acc[mi][ni][0], acc[mi][ni][1], acc[mi][ni][2], acc[mi][ni][3],
                        a0, a1, a2, a3, bl[ni][0], bl[ni][1]);
            }
        }
    }

    float* od = g_xz + ((size_t)mblk * 128) * G4 + nblk * 64;
#pragma unroll
    for (int mi = 0; mi < 2; mi++) {
#pragma unroll
        for (int ni = 0; ni < 2; ni++) {
            int row = mb + 16 * mi + g, col = nb + 8 * ni + 2 * tq;
            *(float2*)(od + (size_t)row * G4 + col)       = make_float2(acc[mi][ni][0], acc[mi][ni][1]);
            *(float2*)(od + (size_t)(row + 8) * G4 + col) = make_float2(acc[mi][ni][2], acc[mi][ni][3]);
        }
    }
}

// ================= Phase 2: persistent recurrence (fp16 2-pass mma) =================
// 128 CTAs = 16 batch-groups x 8 col-groups; CTA = 32 batches x 128 gate-cols
// (local col j = gate*32 + u). h exchanged as fp16 (rounded once by producer).
// W split hi/lo fp16 in SMEM (one-time). Fragments via ldmatrix.
#define RC_CTAS 128
#define WS 264     // W smem stride (fp16 elements)
#define AS 264     // A(h) smem stride
#define XSS 132    // xz smem stride (floats)
#define XSBUF (32 * XSS)
#define ZSS 136    // z smem stride (floats)

__global__ __launch_bounds__(256, 1) void lstm_rec(const float* __restrict__ rk,
                                                   const float* __restrict__ dw,
                                                   const float* __restrict__ db,
                                                   float* __restrict__ out) {
    extern __shared__ char smc[];
    __half* Wh = (__half*)smc;                          // [128][264]
    __half* Wl = (__half*)(smc + 67584);
    __half* Ah = (__half*)(smc + 135168);               // [32][264]
    float* xs = (float*)(smc + 152064);                 // [2][32][132]
    float* zs = (float*)(smc + 185856);                 // [32][136]

    int tid   = threadIdx.x;
    int bg    = blockIdx.x >> 3;
    int cg    = blockIdx.x & 7;
    int bbase = bg * 32;
    int ubase = cg * 32;

    // one-time: weight slice -> fp16 hi/lo, layout Wh[j][k], j = gate*32 + u
    for (int i = tid; i < 128 * 256; i += 256) {
        int j = i >> 8, k = i & 255;
        int gate = j >> 5, u = j & 31;
        float v = rk[(size_t)k * G4 + gate * Uu + ubase + u];
        __half h, l; split1(v, h, l);
        Wh[j * WS + k] = h;
        Wl[j * WS + k] = l;
    }

    int w = tid >> 5, lane = tid & 31;
    int g = lane >> 2, tq = lane & 3;
    int nb = 16 * w;                 // warp covers local cols [16w,16w+16)
    int gb = tid >> 3;               // gate-layer batch
    int gu = (tid & 7) * 4;          // gate-layer unit base
    float cst[4] = {0.f, 0.f, 0.f, 0.f};

    // t-invariant ldmatrix lane-address components
    int aRow = lane & 15;
    int aK   = (lane >> 4) * 8;
    int bRow = nb + 8 * (lane >> 4) + (lane & 7);
    int bK   = 8 * ((lane >> 3) & 1);

    // prefetch xz tile for t=0 into xs buf 0
#pragma unroll
    for (int i = 0; i < 4; i++) {
        int flat4 = tid + 256 * i;
        int bbq = flat4 >> 5, rest = flat4 & 31, gg = rest >> 3, u4 = rest & 7;
        const float* gsrc = g_xz + ((size_t)(bbase + bbq) * Tt + 0) * G4 + gg * Uu + ubase + 4 * u4;
        cp_async16(xs + bbq * XSS + gg * 32 + 4 * u4, gsrc);
    }
    asm volatile("cp.async.commit_group;" ::: "memory");

    unsigned target = 0;

    for (int t = 0; t < Tt; t++) {
        int cur = t & 1, nxt = cur ^ 1;

        // stage h (fp16) tile via cp.async: 32 rows x 256 halves = 1024 x 16B chunks
#pragma unroll
        for (int i = 0; i < 4; i++) {
            int c = tid + 256 * i;       // 0..1023
            int row = c >> 5, o = (c & 31) * 8;
            cp_async16(Ah + row * AS + o, &g_hv[cur][bbase + row][o]);
        }
        asm volatile("cp.async.commit_group;" ::: "memory");
        asm volatile("cp.async.wait_group 0;" ::: "memory");   // h + xz(t) done
        __syncthreads();

        // acc init from xz tile
        float acc[2][2][4];
#pragma unroll
        for (int mi = 0; mi < 2; mi++) {
#pragma unroll
            for (int ni = 0; ni < 2; ni++) {
                const float* zp = xs + cur * XSBUF + (16 * mi + g) * XSS + nb + 8 * ni + 2 * tq;
                float2 a = *(const float2*)zp;
                float2 b = *(const float2*)(zp + 8 * XSS);
                acc[mi][ni][0] = a.x; acc[mi][ni][1] = a.y;
                acc[mi][ni][2] = b.x; acc[mi][ni][3] = b.y;
            }
        }

        // K loop: z += h @ Wr (2-pass fp16, ldmatrix fragments)
#pragma unroll 4
        for (int kc = 0; kc < 256; kc += 16) {
            unsigned bh0, bh1, bh2, bh3, bl0, bl1, bl2, bl3;
            ldsm4(bh0, bh1, bh2, bh3, Wh + bRow * WS + kc + bK);
            ldsm4(bl0, bl1, bl2, bl3, Wl + bRow * WS + kc + bK);
#pragma unroll
            for (int mi = 0; mi < 2; mi++) {
                unsigned a0, a1, a2, a3;
                ldsm4(a0, a1, a2, a3, Ah + (16 * mi + aRow) * AS + kc + aK);
                mma_f16(acc[mi][0][0], acc[mi][0][1], acc[mi][0][2], acc[mi][0][3],
                        a0, a1, a2, a3, bh0, bh1);
                mma_f16(acc[mi][1][0], acc[mi][1][1], acc[mi][1][2], acc[mi][1][3],
                        a0, a1, a2, a3, bh2, bh3);
                mma_f16(acc[mi][0][0], acc[mi][0][1], acc[mi][0][2], acc[mi][0][3],
                        a0, a1, a2, a3, bl0, bl1);
                mma_f16(acc[mi][1][0], acc[mi][1][1], acc[mi][1][2], acc[mi][1][3],
                        a0, a1, a2, a3, bl2, bl3);
            }
        }

        // bounce z through SMEM (decouple gate layout from mma fragments)
#pragma unroll
        for (int mi = 0; mi < 2; mi++) {
#pragma unroll
            for (int ni = 0; ni < 2; ni++) {
                float* zp = zs + (16 * mi + g) * ZSS + nb + 8 * ni + 2 * tq;
                *(float2*)zp             = make_float2(acc[mi][ni][0], acc[mi][ni][1]);
                *(float2*)(zp + 8 * ZSS) = make_float2(acc[mi][ni][2], acc[mi][ni][3]);
            }
        }
        __syncthreads();

        // gate layer: thread -> (batch gb, units gu..gu+3); h rounded to fp16 once
        {
            const float* zr = zs + gb * ZSS + gu;
            float4 zi = *(const float4*)(zr + 0);
            float4 zf = *(const float4*)(zr + 32);
            float4 zg = *(const float4*)(zr + 64);
            float4 zo = *(const float4*)(zr + 96);
            float zia[4] = {zi.x, zi.y, zi.z, zi.w};
            float zfa[4] = {zf.x, zf.y, zf.z, zf.w};
            float zga[4] = {zg.x, zg.y, zg.z, zg.w};
            float zoa[4] = {zo.x, zo.y, zo.z, zo.w};
            __half hn4[4];
#pragma unroll
            for (int e = 0; e < 4; e++) {
                float ig = 1.f / (1.f + __expf(-zia[e]));
                float fg = 1.f / (1.f + __expf(-zfa[e]));
                float gg = fmaxf(zga[e], 0.f);
                float og = 1.f / (1.f + __expf(-zoa[e]));
                float cn = fg * cst[e] + ig * gg;
                cst[e] = cn;
                hn4[e] = __float2half_rn(og * fmaxf(cn, 0.f));
            }
            *(uint2*)(&g_hv[nxt][bbase + gb][ubase + gu]) =
                make_uint2(pk2(hn4[0], hn4[1]), pk2(hn4[2], hn4[3]));
        }

        // prefetch xz tile for t+1
        if (t + 1 < Tt) {
#pragma unroll
            for (int i = 0; i < 4; i++) {
                int flat4 = tid + 256 * i;
                int bbq = flat4 >> 5, rest = flat4 & 31, gg = rest >> 3, u4 = rest & 7;
                const float* gsrc = g_xz + ((size_t)(bbase + bbq) * Tt + (t + 1)) * G4 + gg * Uu + ubase + 4 * u4;
                cp_async16(xs + nxt * XSBUF + bbq * XSS + gg * 32 + 4 * u4, gsrc);
            }
            asm volatile("cp.async.commit_group;" ::: "memory");
        }

        // per-batch-group barrier (8 CTAs share one counter)
        __syncthreads();
        if (tid == 0) {
            __threadfence();
            atomicAdd(&g_barg[bg][0], 1u);
            target += 8;
            while (*((volatile unsigned*)&g_barg[bg][0]) < target) { }
            __threadfence();
        }
        __syncthreads();
    }

    // final dense: out[b] = h_T[b,:] . dw + db  (T even -> final h in buffer 0)
    if (cg == 0) {
        int b = tid >> 3, r = tid & 7;
        const __half* hv = &g_hv[0][bbase + b][0];
        float s = 0.f;
#pragma unroll
        for (int j = 0; j < 32; j++) {
            int u = r + 8 * j;
            s += __half2float(hv[u]) * dw[u];
        }
        s += __shfl_down_sync(0xffffffffu, s, 4);
        s += __shfl_down_sync(0xffffffffu, s, 2);
        s += __shfl_down_sync(0xffffffffu, s, 1);
        if (r == 0) out[bbase + b] = s + db[0];
    }
}

// ---------------- launch ----------------
extern "C" void kernel_launch(void* const* d_in, const int* in_sizes, int n_in,
                              void* d_out, int out_size) {
    const float* x    = (const float*)d_in[0];
    const float* wk   = (const float*)d_in[1];
    const float* rk   = (const float*)d_in[2];
    const float* bias = (const float*)d_in[3];
    const float* dw   = (const float*)d_in[4];
    const float* db   = (const float*)d_in[5];
    float* out = (float*)d_out;

    const int smem1 = 69632;    // phase-1: A [128][136] + B 2x[64][136] fp16
    const int smem2 = 203264;   // phase-2: W hi/lo + A + xs + zs
    cudaFuncSetAttribute(xz_gemm,  cudaFuncAttributeMaxDynamicSharedMemorySize, smem1);
    cudaFuncSetAttribute(lstm_rec, cudaFuncAttributeMaxDynamicSharedMemorySize, smem2);

    reset_kernel<<<(Bb * Uu + 255) / 256, 256>>>();
    xz_gemm<<<dim3(G4 / 64, (Bb * Tt) / 128), 512, smem1>>>(x, wk, bias);
    lstm_rec<<<RC_CTAS, 256, smem2>>>(rk, dw, db, out);
}

// round 12
// speedup vs baseline: 1.3490x; 1.1448x over previous
#include <cuda_runtime.h>
#include <cuda_fp16.h>
#include <cstdint>
#include <cstddef>

#define Bb 512
#define Tt 512
#define Ff 128
#define Uu 256
#define G4 1024   // 4*U

// ---------------- device scratch ----------------
__device__ float g_xz[(size_t)Bb * Tt * G4];          // precomputed x@kernel+bias
__device__ __half g_hv[2][Bb][Uu];                    // h (fp16), double buffered
__device__ unsigned g_barg[16][32];                   // per-batch-group barrier

__global__ void reset_kernel() {
    int i = blockIdx.x * blockDim.x + threadIdx.x;
    if (i < Bb * Uu) (&g_hv[0][0][0])[i] = __ushort_as_half(0);
    if (i < 16 * 32) (&g_barg[0][0])[i] = 0u;
}

// ---------------- helpers ----------------
__device__ __forceinline__ void mma_f16(float& d0, float& d1, float& d2, float& d3,
                                        unsigned a0, unsigned a1, unsigned a2, unsigned a3,
                                        unsigned b0, unsigned b1) {
    asm volatile("mma.sync.aligned.m16n8k16.row.col.f32.f16.f16.f32 "
                 "{%0,%1,%2,%3}, {%4,%5,%6,%7}, {%8,%9}, {%0,%1,%2,%3};"
                 : "+f"(d0), "+f"(d1), "+f"(d2), "+f"(d3)
                 : "r"(a0), "r"(a1), "r"(a2), "r"(a3), "r"(b0), "r"(b1));
}
__device__ __forceinline__ unsigned pk2(__half x, __half y) {
    __half2 t; t.x = x; t.y = y;
    return *reinterpret_cast<unsigned*>(&t);
}
__device__ __forceinline__ void cp_async16(void* sdst, const void* gsrc) {
    unsigned sa = (unsigned)__cvta_generic_to_shared(sdst);
    asm volatile("cp.async.cg.shared.global [%0], [%1], 16;" :: "r"(sa), "l"(gsrc));
}
__device__ __forceinline__ void ldsm4(unsigned& r0, unsigned& r1, unsigned& r2, unsigned& r3,
                                      const void* p) {
    unsigned sa = (unsigned)__cvta_generic_to_shared(p);
    asm volatile("ldmatrix.sync.aligned.m8n8.x4.shared.b16 {%0,%1,%2,%3}, [%4];"
                 : "=r"(r0), "=r"(r1), "=r"(r2), "=r"(r3) : "r"(sa));
}

// ================= Phase 1: XZ = x @ kernel + bias (fp16 1-pass mma) =================
// CTA tile 128M x 64N, K=128. 512 threads = 16 warps (4x4), warp tile 32x16.
#define P1_STR 136

__global__ __launch_bounds__(512, 2) void xz_gemm(const float* __restrict__ x,
                                                  const float* __restrict__ wk,
                                                  const float* __restrict__ bias) {
    extern __shared__ char smc[];
    __half* Ax  = (__half*)smc;                        // [128][136]
    __half* Bx  = (__half*)(smc + 34816);              // [64 n][136 k]

    int tid  = threadIdx.x;
    int nblk = blockIdx.x, mblk = blockIdx.y;
    const float* xblk = x + (size_t)mblk * 128 * Ff;
    const float* wcol = wk + (size_t)nblk * 64;

    // A fill: x tile [128][128] fp32 -> fp16
    {
        int r = tid >> 2, q = tid & 3;
        const float* xr = xblk + (size_t)r * Ff;
#pragma unroll
        for (int jj = 0; jj < 8; jj++) {
            int col = 4 * q + 16 * jj;
            float4 v = *(const float4*)(xr + col);
            *(unsigned*)(Ax + r * P1_STR + col)     = pk2(__float2half_rn(v.x), __float2half_rn(v.y));
            *(unsigned*)(Ax + r * P1_STR + col + 2) = pk2(__float2half_rn(v.z), __float2half_rn(v.w));
        }
    }
    // B fill: Bs[n][k] = wk[k][nblk*64+n] -> fp16
#pragma unroll
    for (int i = 0; i < 16; i++) {
        int flat = tid + 512 * i;
        int k = flat >> 6, n = flat & 63;
        Bx[n * P1_STR + k] = __float2half_rn(wcol[(size_t)k * G4 + n]);
    }
    __syncthreads();

    int w = tid >> 5, lane = tid & 31;
    int wm = w >> 2, wn = w & 3;
    int g = lane >> 2, tq = lane & 3;
    int mb = 32 * wm, nb = 16 * wn;

    float acc[2][2][4];
#pragma unroll
    for (int ni = 0; ni < 2; ni++) {
        float2 bv = *(const float2*)(bias + nblk * 64 + nb + 8 * ni + 2 * tq);
#pragma unroll
        for (int mi = 0; mi < 2; mi++) {
            acc[mi][ni][0] = bv.x; acc[mi][ni][1] = bv.y;
            acc[mi][ni][2] = bv.x; acc[mi][ni][3] = bv.y;
        }
    }

#pragma unroll 4
    for (int kc = 0; kc < 128; kc += 16) {
        unsigned bh[2][2];
#pragma unroll
        for (int ni = 0; ni < 2; ni++) {
            const __half* bp = Bx + (nb + 8 * ni + g) * P1_STR + kc + 2 * tq;
            bh[ni][0] = *(const unsigned*)bp;
            bh[ni][1] = *(const unsigned*)(bp + 8);
        }
#pragma unroll
        for (int mi = 0; mi < 2; mi++) {
            const __half* ap = Ax + (mb + 16 * mi + g) * P1_STR + kc + 2 * tq;
            unsigned a0 = *(const unsigned*)ap;
            unsigned a1 = *(const unsigned*)(ap + 8 * P1_STR);
            unsigned a2 = *(const unsigned*)(ap + 8);
            unsigned a3 = *(const unsigned*)(ap + 8 * P1_STR + 8);
#pragma unroll
            for (int ni = 0; ni < 2; ni++)
                mma_f16(acc[mi][ni][0], acc[mi][ni][1], acc[mi][ni][2], acc[mi][ni][3],
                        a0, a1, a2, a3, bh[ni][0], bh[ni][1]);
        }
    }

    float* od = g_xz + ((size_t)mblk * 128) * G4 + nblk * 64;
#pragma unroll
    for (int mi = 0; mi < 2; mi++) {
#pragma unroll
        for (int ni = 0; ni < 2; ni++) {
            int row = mb + 16 * mi + g, col = nb + 8 * ni + 2 * tq;
            *(float2*)(od + (size_t)row * G4 + col)       = make_float2(acc[mi][ni][0], acc[mi][ni][1]);
            *(float2*)(od + (size_t)(row + 8) * G4 + col) = make_float2(acc[mi][ni][2], acc[mi][ni][3]);
        }
    }
}

// ================= Phase 2: persistent recurrence (fp16 1-pass mma) =================
// 128 CTAs = 16 batch-groups x 8 col-groups; CTA = 32 batches x 128 gate-cols
// (local col j = gate*32 + u). h exchanged as fp16; W rounded to fp16 (one-time).
#define RC_CTAS 128
#define WS 264     // W smem stride (fp16 elements)
#define AS 264     // A(h) smem stride
#define XSS 132    // xz smem stride (floats)
#define XSBUF (32 * XSS)
#define ZSS 136    // z smem stride (floats)

__global__ __launch_bounds__(256, 1) void lstm_rec(const float* __restrict__ rk,
                                                   const float* __restrict__ dw,
                                                   const float* __restrict__ db,
                                                   float* __restrict__ out) {
    extern __shared__ char smc[];
    __half* Wh = (__half*)smc;                          // [128][264]
    __half* Ah = (__half*)(smc + 67584);                // [32][264]
    float* xs = (float*)(smc + 84480);                  // [2][32][132]
    float* zs = (float*)(smc + 118272);                 // [32][136]

    int tid   = threadIdx.x;
    int bg    = blockIdx.x >> 3;
    int cg    = blockIdx.x & 7;
    int bbase = bg * 32;
    int ubase = cg * 32;

    // one-time: weight slice -> fp16, layout Wh[j][k], j = gate*32 + u
    for (int i = tid; i < 128 * 256; i += 256) {
        int j = i >> 8, k = i & 255;
        int gate = j >> 5, u = j & 31;
        Wh[j * WS + k] = __float2half_rn(rk[(size_t)k * G4 + gate * Uu + ubase + u]);
    }

    int w = tid >> 5, lane = tid & 31;
    int g = lane >> 2, tq = lane & 3;
    int nb = 16 * w;                 // warp covers local cols [16w,16w+16)
    int gb = tid >> 3;               // gate-layer batch
    int gu = (tid & 7) * 4;          // gate-layer unit base
    float cst[4] = {0.f, 0.f, 0.f, 0.f};

    // t-invariant ldmatrix lane-address components
    int aRow = lane & 15;
    int aK   = (lane >> 4) * 8;
    int bRow = nb + 8 * (lane >> 4) + (lane & 7);
    int bK   = 8 * ((lane >> 3) & 1);

    // prefetch xz tile for t=0 into xs buf 0
#pragma unroll
    for (int i = 0; i < 4; i++) {
        int flat4 = tid + 256 * i;
        int bbq = flat4 >> 5, rest = flat4 & 31, gg = rest >> 3, u4 = rest & 7;
        const float* gsrc = g_xz + ((size_t)(bbase + bbq) * Tt + 0) * G4 + gg * Uu + ubase + 4 * u4;
        cp_async16(xs + bbq * XSS + gg * 32 + 4 * u4, gsrc);
    }
    asm volatile("cp.async.commit_group;" ::: "memory");

    unsigned target = 0;

    for (int t = 0; t < Tt; t++) {
        int cur = t & 1, nxt = cur ^ 1;

        // stage h (fp16) tile via cp.async: 32 rows x 256 halves = 1024 x 16B chunks
#pragma unroll
        for (int i = 0; i < 4; i++) {
            int c = tid + 256 * i;       // 0..1023
            int row = c >> 5, o = (c & 31) * 8;
            cp_async16(Ah + row * AS + o, &g_hv[cur][bbase + row][o]);
        }
        asm volatile("cp.async.commit_group;" ::: "memory");
        asm volatile("cp.async.wait_group 0;" ::: "memory");   // h + xz(t) done
        __syncthreads();

        // acc init from xz tile
        float acc[2][2][4];
#pragma unroll
        for (int mi = 0; mi < 2; mi++) {
#pragma unroll
            for (int ni = 0; ni < 2; ni++) {
                const float* zp = xs + cur * XSBUF + (16 * mi + g) * XSS + nb + 8 * ni + 2 * tq;
                float2 a = *(const float2*)zp;
                float2 b = *(const float2*)(zp + 8 * XSS);
                acc[mi][ni][0] = a.x; acc[mi][ni][1] = a.y;
                acc[mi][ni][2] = b.x; acc[mi][ni][3] = b.y;
            }
        }

        // K loop: z += h @ Wr (1-pass fp16, ldmatrix fragments)
#pragma unroll 4
        for (int kc = 0; kc < 256; kc += 16) {
            unsigned bh0, bh1, bh2, bh3;
            ldsm4(bh0, bh1, bh2, bh3, Wh + bRow * WS + kc + bK);
#pragma unroll
            for (int mi = 0; mi < 2; mi++) {
                unsigned a0, a1, a2, a3;
                ldsm4(a0, a1, a2, a3, Ah + (16 * mi + aRow) * AS + kc + aK);
                mma_f16(acc[mi][0][0], acc[mi][0][1], acc[mi][0][2], acc[mi][0][3],
                        a0, a1, a2, a3, bh0, bh1);
                mma_f16(acc[mi][1][0], acc[mi][1][1], acc[mi][1][2], acc[mi][1][3],
                        a0, a1, a2, a3, bh2, bh3);
            }
        }

        // bounce z through SMEM (decouple gate layout from mma fragments)
#pragma unroll
        for (int mi = 0; mi < 2; mi++) {
#pragma unroll
            for (int ni = 0; ni < 2; ni++) {
                float* zp = zs + (16 * mi + g) * ZSS + nb + 8 * ni + 2 * tq;
                *(float2*)zp             = make_float2(acc[mi][ni][0], acc[mi][ni][1]);
                *(float2*)(zp + 8 * ZSS) = make_float2(acc[mi][ni][2], acc[mi][ni][3]);
            }
        }
        __syncthreads();

        // gate layer: thread -> (batch gb, units gu..gu+3); h rounded to fp16 once
        {
            const float* zr = zs + gb * ZSS + gu;
            float4 zi = *(const float4*)(zr + 0);
            float4 zf = *(const float4*)(zr + 32);
            float4 zg = *(const float4*)(zr + 64);
            float4 zo = *(const float4*)(zr + 96);
            float zia[4] = {zi.x, zi.y, zi.z, zi.w};
            float zfa[4] = {zf.x, zf.y, zf.z, zf.w};
            float zga[4] = {zg.x, zg.y, zg.z, zg.w};
            float zoa[4] = {zo.x, zo.y, zo.z, zo.w};
            __half hn4[4];
#pragma unroll
            for (int e = 0; e < 4; e++) {
                float ig = 1.f / (1.f + __expf(-zia[e]));
                float fg = 1.f / (1.f + __expf(-zfa[e]));
                float gg = fmaxf(zga[e], 0.f);
                float og = 1.f / (1.f + __expf(-zoa[e]));
                float cn = fg * cst[e] + ig * gg;
                cst[e] = cn;
                hn4[e] = __float2half_rn(og * fmaxf(cn, 0.f));
            }
            *(uint2*)(&g_hv[nxt][bbase + gb][ubase + gu]) =
                make_uint2(pk2(hn4[0], hn4[1]), pk2(hn4[2], hn4[3]));
        }

        // prefetch xz tile for t+1
        if (t + 1 < Tt) {
#pragma unroll
            for (int i = 0; i < 4; i++) {
                int flat4 = tid + 256 * i;
                int bbq = flat4 >> 5, rest = flat4 & 31, gg = rest >> 3, u4 = rest & 7;
                const float* gsrc = g_xz + ((size_t)(bbase + bbq) * Tt + (t + 1)) * G4 + gg * Uu + ubase + 4 * u4;
                cp_async16(xs + nxt * XSBUF + bbq * XSS + gg * 32 + 4 * u4, gsrc);
            }
            asm volatile("cp.async.commit_group;" ::: "memory");
        }

        // per-batch-group barrier (8 CTAs share one counter)
        __syncthreads();
        if (tid == 0) {
            __threadfence();
            atomicAdd(&g_barg[bg][0], 1u);
            target += 8;
            while (*((volatile unsigned*)&g_barg[bg][0]) < target) { }
            __threadfence();
        }
        __syncthreads();
    }

    // final dense: out[b] = h_T[b,:] . dw + db  (T even -> final h in buffer 0)
    if (cg == 0) {
        int b = tid >> 3, r = tid & 7;
        const __half* hv = &g_hv[0][bbase + b][0];
        float s = 0.f;
#pragma unroll
        for (int j = 0; j < 32; j++) {
            int u = r + 8 * j;
            s += __half2float(hv[u]) * dw[u];
        }
        s += __shfl_down_sync(0xffffffffu, s, 4);
        s += __shfl_down_sync(0xffffffffu, s, 2);
        s += __shfl_down_sync(0xffffffffu, s, 1);
        if (r == 0) out[bbase + b] = s + db[0];
    }
}

// ---------------- launch ----------------
extern "C" void kernel_launch(void* const* d_in, const int* in_sizes, int n_in,
                              void* d_out, int out_size) {
    const float* x    = (const float*)d_in[0];
    const float* wk   = (const float*)d_in[1];
    const float* rk   = (const float*)d_in[2];
    const float* bias = (const float*)d_in[3];
    const float* dw   = (const float*)d_in[4];
    const float* db   = (const float*)d_in[5];
    float* out = (float*)d_out;

    const int smem1 = 52224;    // phase-1: A [128][136] + B [64][136] fp16
    const int smem2 = 135680;   // phase-2: W + A + xs + zs
    cudaFuncSetAttribute(xz_gemm,  cudaFuncAttributeMaxDynamicSharedMemorySize, smem1);
    cudaFuncSetAttribute(lstm_rec, cudaFuncAttributeMaxDynamicSharedMemorySize, smem2);

    reset_kernel<<<(Bb * Uu + 255) / 256, 256>>>();
    xz_gemm<<<dim3(G4 / 64, (Bb * Tt) / 128), 512, smem1>>>(x, wk, bias);
    lstm_rec<<<RC_CTAS, 256, smem2>>>(rk, dw, db, out);
}